// round 12
// baseline (speedup 1.0000x reference)
#include <cuda_runtime.h>
#include <math.h>
#include <stdint.h>

#define BATCH 2
#define CDIM 192
#define HH 192
#define WW 192
#define HWSZ (HH*WW)      // 36864
#define OC3 (3*CDIM)      // 576
#define NH 4
#define HD 48
#define ACH 144           // attn chunks per (b,h): 256 cols each

#define ASTRIDE 36        // As row stride (floats)
#define BSTRIDE 264       // Bs row stride (floats)
#define STAGE_FLOATS (64*ASTRIDE + 32*BSTRIDE)   // 10752
#define GEMM_SMEM_BYTES (2 * STAGE_FLOATS * 4)   // 86016

#define QSTRIDE 260       // attn smem tile stride: 260 % 32 == 4 -> conflict-free
#define ATTN_SMEM_FLOATS (2 * HD * QSTRIDE + HD * HD)
#define ATTN_SMEM_BYTES (ATTN_SMEM_FLOATS * 4)   // 109,056

// ---- scratch (device globals; no allocations allowed) ----
__device__ float g_qkv[(long)BATCH*OC3*HWSZ];   // after 1x1 conv
__device__ float g_dw [(long)BATCH*OC3*HWSZ];   // after depthwise conv
__device__ float g_xt [(long)BATCH*CDIM*HWSZ];  // x pre-rounded to tf32
__device__ float g_wqt[OC3*CDIM];                // w_qkv pre-rounded to tf32
__device__ float g_sumsq[BATCH*2*CDIM];          // per-channel sum of squares (q,k)
__device__ float g_attn_part[(long)BATCH*NH*ACH*HD*HD]; // per-chunk partial q.k^T
__device__ float g_attn_r[BATCH*NH*HD*HD];       // reduced raw attn
__device__ float g_attn_s[BATCH*NH*HD*HD];       // softmaxed
__device__ float g_W2[BATCH*CDIM*CDIM];          // w_proj @ blockdiag(attn), tf32-rounded

__device__ __forceinline__ float cvt_tf32(float x) {
    unsigned u;
    asm("cvt.rna.tf32.f32 %0, %1;" : "=r"(u) : "f"(x));
    return __uint_as_float(u);
}
__device__ __forceinline__ void cp_async16(uint32_t dst, const void* src) {
    asm volatile("cp.async.cg.shared.global [%0], [%1], 16;" :: "r"(dst), "l"(src));
}
__device__ __forceinline__ void cp_commit() {
    asm volatile("cp.async.commit_group;");
}
template <int N>
__device__ __forceinline__ void cp_wait() {
    asm volatile("cp.async.wait_group %0;" :: "n"(N));
}

// ---------------------------------------------------------------
// pre-round x and w_qkv to tf32 (RNA); also zero sumsq accumulators.
// ---------------------------------------------------------------
__global__ __launch_bounds__(256) void cvt_kernel(
    const float4* __restrict__ x, const float4* __restrict__ wq)
{
    const long NX = (long)BATCH*CDIM*HWSZ/4;
    float4* xt = (float4*)g_xt;
    float4* wt = (float4*)g_wqt;
    long i0 = (long)blockIdx.x * blockDim.x + threadIdx.x;
    if (i0 < BATCH*2*CDIM) g_sumsq[i0] = 0.f;
    for (long i = i0; i < NX; i += (long)gridDim.x * blockDim.x) {
        float4 v = x[i];
        v.x = cvt_tf32(v.x); v.y = cvt_tf32(v.y);
        v.z = cvt_tf32(v.z); v.w = cvt_tf32(v.w);
        xt[i] = v;
    }
    if (i0 < OC3*CDIM/4) {
        float4 v = wq[i0];
        v.x = cvt_tf32(v.x); v.y = cvt_tf32(v.y);
        v.z = cvt_tf32(v.z); v.w = cvt_tf32(v.w);
        wt[i0] = v;
    }
}

// ---------------------------------------------------------------
// TF32 tensor-core GEMM, cp.async double-buffered, 64x256xBK32.
// ---------------------------------------------------------------
__global__ __launch_bounds__(256, 2) void tf32_gemm_kernel(
    const float* __restrict__ A, const float* __restrict__ Bm, float* __restrict__ Cm,
    long aStride, long bStride, long cStride)
{
    extern __shared__ float smem_[];

    const int t = threadIdx.x;
    const float* Ab = A  + (long)blockIdx.z * aStride + (long)blockIdx.y * 64 * 192;
    const float* Bb = Bm + (long)blockIdx.z * bStride + blockIdx.x * 256;
    float*       Cb = Cm + (long)blockIdx.z * cStride;

    const int arow0 = t >> 3,          akq0 = t & 7;
    const int arow1 = (t + 256) >> 3,  akq1 = t & 7;
    const int bk = t >> 5;
    const int bc = (t & 31);

    const int w = t >> 5, l = t & 31;
    const int mw = (w >> 2) * 32;
    const int nw = (w & 3) * 64;
    const int g = l >> 2, q_ = l & 3;

    uint32_t smem_u = (uint32_t)__cvta_generic_to_shared(smem_);

    float acc[2][8][4];
#pragma unroll
    for (int mt = 0; mt < 2; mt++)
#pragma unroll
        for (int nt = 0; nt < 8; nt++)
#pragma unroll
            for (int c = 0; c < 4; c++) acc[mt][nt][c] = 0.f;

    auto load_stage = [&](int stage, int k0) {
        uint32_t As_u = smem_u + stage * STAGE_FLOATS * 4;
        uint32_t Bs_u = As_u + 64 * ASTRIDE * 4;
        cp_async16(As_u + (arow0 * ASTRIDE + akq0 * 4) * 4,
                   Ab + (long)arow0 * 192 + k0 + akq0 * 4);
        cp_async16(As_u + (arow1 * ASTRIDE + akq1 * 4) * 4,
                   Ab + (long)arow1 * 192 + k0 + akq1 * 4);
#pragma unroll
        for (int r = 0; r < 4; r++) {
            const int krow = bk + r * 8;
            const float* src = Bb + (long)(k0 + krow) * HWSZ;
            uint32_t drow = Bs_u + krow * BSTRIDE * 4;
            cp_async16(drow + bc * 16,        src + bc * 4);
            cp_async16(drow + (bc + 32) * 16, src + (bc + 32) * 4);
        }
        cp_commit();
    };

    load_stage(0, 0);

    for (int kt = 0; kt < 6; kt++) {
        if (kt < 5) load_stage((kt + 1) & 1, (kt + 1) * 32);
        if (kt < 5) cp_wait<1>(); else cp_wait<0>();
        __syncthreads();

        const float* As = smem_ + (kt & 1) * STAGE_FLOATS;
        const float* Bs = As + 64 * ASTRIDE;

#pragma unroll
        for (int s = 0; s < 4; s++) {
            const int kb = s * 8;
            unsigned a[2][4], bf[8][2];
#pragma unroll
            for (int mt = 0; mt < 2; mt++) {
                const float* ar = As + (mw + mt * 16 + g) * ASTRIDE + kb;
                a[mt][0] = __float_as_uint(ar[q_]);
                a[mt][1] = __float_as_uint(ar[8 * ASTRIDE + q_]);
                a[mt][2] = __float_as_uint(ar[q_ + 4]);
                a[mt][3] = __float_as_uint(ar[8 * ASTRIDE + q_ + 4]);
            }
#pragma unroll
            for (int nt = 0; nt < 8; nt++) {
                bf[nt][0] = __float_as_uint(Bs[(kb + q_) * BSTRIDE + nw + nt * 8 + g]);
                bf[nt][1] = __float_as_uint(Bs[(kb + q_ + 4) * BSTRIDE + nw + nt * 8 + g]);
            }
#pragma unroll
            for (int mt = 0; mt < 2; mt++)
#pragma unroll
                for (int nt = 0; nt < 8; nt++) {
                    float* d = acc[mt][nt];
                    asm volatile(
                        "mma.sync.aligned.m16n8k8.row.col.f32.tf32.tf32.f32 "
                        "{%0,%1,%2,%3}, {%4,%5,%6,%7}, {%8,%9}, {%0,%1,%2,%3};\n"
                        : "+f"(d[0]), "+f"(d[1]), "+f"(d[2]), "+f"(d[3])
                        : "r"(a[mt][0]), "r"(a[mt][1]), "r"(a[mt][2]), "r"(a[mt][3]),
                          "r"(bf[nt][0]), "r"(bf[nt][1]));
                }
        }
        __syncthreads();
    }

    const int colb = blockIdx.x * 256 + nw;
    const int rowb = blockIdx.y * 64 + mw;
#pragma unroll
    for (int mt = 0; mt < 2; mt++)
#pragma unroll
        for (int nt = 0; nt < 8; nt++) {
            const int row = rowb + mt * 16 + g;
            const int col = colb + nt * 8 + 2 * q_;
            *(float2*)(Cb + (long)row * HWSZ + col) =
                make_float2(acc[mt][nt][0], acc[mt][nt][1]);
            *(float2*)(Cb + (long)(row + 8) * HWSZ + col) =
                make_float2(acc[mt][nt][2], acc[mt][nt][3]);
        }
}

// ---------------------------------------------------------------
// Depthwise 3x3 SAME, 64x64 tile, 16 outputs/thread. (R9 version —
// read-side vectorization is what matters, keep tx-aligned reads.)
// grid: (3, 3, BATCH*576), block 256
// ---------------------------------------------------------------
__global__ __launch_bounds__(256) void dw_kernel(const float* __restrict__ wdw)
{
    const int bc = blockIdx.z;
    const int c  = bc % OC3;
    const int b  = bc / OC3;
    const float* __restrict__ p = g_qkv + (long)bc * HWSZ;
    float*       __restrict__ o = g_dw  + (long)bc * HWSZ;

    __shared__ float tile[66][68];     // interior at [1..64][1..64]
    const int x0 = blockIdx.x * 64, y0 = blockIdx.y * 64;
    const int tid = threadIdx.x;

    // interior 64x64: 4 float4 loads per thread, zero predicates
    {
        const int col  = (tid & 15) * 4;
        const int row0 = tid >> 4;
#pragma unroll
        for (int rr = 0; rr < 4; rr++) {
            const int row = row0 + rr * 16;
            float4 v = *(const float4*)(p + (long)(y0 + row) * WW + x0 + col);
            tile[row + 1][col + 1] = v.x;
            tile[row + 1][col + 2] = v.y;
            tile[row + 1][col + 3] = v.z;
            tile[row + 1][col + 4] = v.w;
        }
    }
    // halo strips: 4 x 64 elements
    {
        const int qd = tid >> 6, i = tid & 63;
        int gy, gx; float* dst;
        if (qd == 0)      { gy = y0 - 1;  gx = x0 + i;  dst = &tile[0][i + 1]; }
        else if (qd == 1) { gy = y0 + 64; gx = x0 + i;  dst = &tile[65][i + 1]; }
        else if (qd == 2) { gy = y0 + i;  gx = x0 - 1;  dst = &tile[i + 1][0]; }
        else              { gy = y0 + i;  gx = x0 + 64; dst = &tile[i + 1][65]; }
        *dst = (gy >= 0 && gy < HH && gx >= 0 && gx < WW) ? p[gy * WW + gx] : 0.f;
    }
    // corners
    if (tid < 4) {
        const int cy = (tid & 1) ? 65 : 0;
        const int cx = (tid & 2) ? 65 : 0;
        const int gy = y0 + ((tid & 1) ? 64 : -1);
        const int gx = x0 + ((tid & 2) ? 64 : -1);
        tile[cy][cx] = (gy >= 0 && gy < HH && gx >= 0 && gx < WW)
                           ? p[gy * WW + gx] : 0.f;
    }
    __syncthreads();

    float wv[9];
#pragma unroll
    for (int i = 0; i < 9; i++) wv[i] = __ldg(&wdw[c * 9 + i]);

    const int tx = (tid & 15) * 4;
    const int ty = (tid >> 4) * 4;
    const bool isqk = (c < 2 * CDIM);

    float ssq = 0.f;
#pragma unroll
    for (int i = 0; i < 4; i++) {
        float r0[6], r1[6], r2[6];
#pragma unroll
        for (int j = 0; j < 6; j++) {
            r0[j] = tile[ty + i    ][tx + j];
            r1[j] = tile[ty + i + 1][tx + j];
            r2[j] = tile[ty + i + 2][tx + j];
        }
        float4 ov;
        float* op = (float*)&ov;
#pragma unroll
        for (int j = 0; j < 4; j++) {
            float s = 0.f;
            s = fmaf(wv[0], r0[j],     s);
            s = fmaf(wv[1], r0[j + 1], s);
            s = fmaf(wv[2], r0[j + 2], s);
            s = fmaf(wv[3], r1[j],     s);
            s = fmaf(wv[4], r1[j + 1], s);
            s = fmaf(wv[5], r1[j + 2], s);
            s = fmaf(wv[6], r2[j],     s);
            s = fmaf(wv[7], r2[j + 1], s);
            s = fmaf(wv[8], r2[j + 2], s);
            ssq = fmaf(s, s, ssq);
            op[j] = isqk ? s : cvt_tf32(s);
        }
        *(float4*)(o + (long)(y0 + ty + i) * WW + x0 + tx) = ov;
    }

    if (isqk) {
#pragma unroll
        for (int off = 16; off > 0; off >>= 1)
            ssq += __shfl_xor_sync(0xffffffffu, ssq, off);
        __shared__ float wsum[8];
        const int lane = tid & 31, wrp = tid >> 5;
        if (lane == 0) wsum[wrp] = ssq;
        __syncthreads();
        if (tid == 0) {
            float tot = 0.f;
#pragma unroll
            for (int i = 0; i < 8; i++) tot += wsum[i];
            atomicAdd(&g_sumsq[b * 2 * CDIM + c], tot);
        }
    }
}

// ---------------------------------------------------------------
// attn partials via tensor cores, split-tf32, SMEM-STAGED.
// Block stages q,k tiles [48 x 256] with coalesced float4 loads,
// then each warp computes its 32-col slice (4 k-steps of 8) from
// smem (stride 260 -> conflict-free fragment reads).
// grid: (ACH=144, BATCH*NH), block 256, dynamic smem 106.5KB
// ---------------------------------------------------------------
__global__ __launch_bounds__(256, 2) void attn_kernel()
{
    extern __shared__ float asm_[];
    float* qs  = asm_;                       // [48][260]
    float* ks_ = asm_ + HD * QSTRIDE;        // [48][260]
    float* buf = asm_ + 2 * HD * QSTRIDE;    // [48*48]

    const int bh = blockIdx.y;
    const int b = bh >> 2, h = bh & 3;
    const float* __restrict__ qbase = g_dw + ((long)b * OC3 + h * HD) * HWSZ;
    const float* __restrict__ kbase = g_dw + ((long)b * OC3 + CDIM + h * HD) * HWSZ;

    const int t = threadIdx.x;
    const int w = t >> 5, l = t & 31;
    const int g = l >> 2, q_ = l & 3;
    const int n0 = blockIdx.x * 256;

    for (int i = t; i < HD * HD; i += 256) buf[i] = 0.f;

    // coalesced stage: 48 rows x 64 float4 per tensor, 12 iters/thread
    for (int i = t; i < HD * 64; i += 256) {
        const int row = i >> 6, c4 = (i & 63) * 4;
        *(float4*)&qs[row * QSTRIDE + c4] =
            *(const float4*)(qbase + (long)row * HWSZ + n0 + c4);
        *(float4*)&ks_[row * QSTRIDE + c4] =
            *(const float4*)(kbase + (long)row * HWSZ + n0 + c4);
    }
    __syncthreads();

    float acc[3][6][4];
#pragma unroll
    for (int mt = 0; mt < 3; mt++)
#pragma unroll
        for (int nt = 0; nt < 6; nt++)
#pragma unroll
            for (int c = 0; c < 4; c++) acc[mt][nt][c] = 0.f;

#pragma unroll
    for (int kss = 0; kss < 4; kss++) {
        const int nn = w * 32 + kss * 8 + q_;
        unsigned ah[3][4], al[3][4], bhx[6][2], blx[6][2];
#pragma unroll
        for (int mt = 0; mt < 3; mt++) {
            const float* p0 = qs + (mt * 16 + g) * QSTRIDE + nn;
            const float* p1 = p0 + 8 * QSTRIDE;
            float v0 = p0[0], v1 = p1[0], v2 = p0[4], v3 = p1[4];
            float h0 = cvt_tf32(v0), h1 = cvt_tf32(v1);
            float h2 = cvt_tf32(v2), h3 = cvt_tf32(v3);
            ah[mt][0] = __float_as_uint(h0); al[mt][0] = __float_as_uint(cvt_tf32(v0 - h0));
            ah[mt][1] = __float_as_uint(h1); al[mt][1] = __float_as_uint(cvt_tf32(v1 - h1));
            ah[mt][2] = __float_as_uint(h2); al[mt][2] = __float_as_uint(cvt_tf32(v2 - h2));
            ah[mt][3] = __float_as_uint(h3); al[mt][3] = __float_as_uint(cvt_tf32(v3 - h3));
        }
#pragma unroll
        for (int nt = 0; nt < 6; nt++) {
            const float* p = ks_ + (nt * 8 + g) * QSTRIDE + nn;
            float v0 = p[0], v1 = p[4];
            float h0 = cvt_tf32(v0), h1 = cvt_tf32(v1);
            bhx[nt][0] = __float_as_uint(h0); blx[nt][0] = __float_as_uint(cvt_tf32(v0 - h0));
            bhx[nt][1] = __float_as_uint(h1); blx[nt][1] = __float_as_uint(cvt_tf32(v1 - h1));
        }
#pragma unroll
        for (int mt = 0; mt < 3; mt++)
#pragma unroll
            for (int nt = 0; nt < 6; nt++) {
                float* d = acc[mt][nt];
                asm volatile(
                    "mma.sync.aligned.m16n8k8.row.col.f32.tf32.tf32.f32 "
                    "{%0,%1,%2,%3}, {%4,%5,%6,%7}, {%8,%9}, {%0,%1,%2,%3};\n"
                    : "+f"(d[0]), "+f"(d[1]), "+f"(d[2]), "+f"(d[3])
                    : "r"(ah[mt][0]), "r"(ah[mt][1]), "r"(ah[mt][2]), "r"(ah[mt][3]),
                      "r"(bhx[nt][0]), "r"(bhx[nt][1]));
                asm volatile(
                    "mma.sync.aligned.m16n8k8.row.col.f32.tf32.tf32.f32 "
                    "{%0,%1,%2,%3}, {%4,%5,%6,%7}, {%8,%9}, {%0,%1,%2,%3};\n"
                    : "+f"(d[0]), "+f"(d[1]), "+f"(d[2]), "+f"(d[3])
                    : "r"(al[mt][0]), "r"(al[mt][1]), "r"(al[mt][2]), "r"(al[mt][3]),
                      "r"(bhx[nt][0]), "r"(bhx[nt][1]));
                asm volatile(
                    "mma.sync.aligned.m16n8k8.row.col.f32.tf32.tf32.f32 "
                    "{%0,%1,%2,%3}, {%4,%5,%6,%7}, {%8,%9}, {%0,%1,%2,%3};\n"
                    : "+f"(d[0]), "+f"(d[1]), "+f"(d[2]), "+f"(d[3])
                    : "r"(ah[mt][0]), "r"(ah[mt][1]), "r"(ah[mt][2]), "r"(ah[mt][3]),
                      "r"(blx[nt][0]), "r"(blx[nt][1]));
            }
    }

#pragma unroll
    for (int mt = 0; mt < 3; mt++)
#pragma unroll
        for (int nt = 0; nt < 6; nt++) {
            const int r0 = mt * 16 + g, c0 = nt * 8 + 2 * q_;
            atomicAdd(&buf[r0 * HD + c0],       acc[mt][nt][0]);
            atomicAdd(&buf[r0 * HD + c0 + 1],   acc[mt][nt][1]);
            atomicAdd(&buf[(r0+8) * HD + c0],   acc[mt][nt][2]);
            atomicAdd(&buf[(r0+8) * HD + c0+1], acc[mt][nt][3]);
        }
    __syncthreads();

    float* op = g_attn_part + ((long)bh * ACH + blockIdx.x) * HD * HD;
    for (int i = t; i < HD * HD; i += 256) op[i] = buf[i];
}

// ---------------------------------------------------------------
// parallel reduce of the ACH partials: grid (9, 8), 256 threads.
// ---------------------------------------------------------------
__global__ __launch_bounds__(256) void reduce_kernel()
{
    const int bh = blockIdx.y;
    const int cell = blockIdx.x * 256 + threadIdx.x;
    const float* pp = g_attn_part + (long)bh * ACH * HD * HD + cell;
    float s = 0.f;
#pragma unroll 8
    for (int c = 0; c < ACH; c++) s += pp[(long)c * HD * HD];
    g_attn_r[bh * HD * HD + cell] = s;
}

// ---------------------------------------------------------------
__global__ void softmax_kernel(const float* __restrict__ log_temp)
{
    const int bh = blockIdx.x;
    const int b = bh >> 2, h = bh & 3;
    __shared__ float nq[HD], nk[HD];
    const int t = threadIdx.x;
    if (t < HD) {
        nq[t] = fmaxf(sqrtf(g_sumsq[b * 2 * CDIM + h * HD + t]), 1e-12f);
        nk[t] = fmaxf(sqrtf(g_sumsq[b * 2 * CDIM + CDIM + h * HD + t]), 1e-12f);
    }
    __syncthreads();
    const float temp = log1pf(expf(log_temp[h])) + 1e-6f;
    if (t < HD) {
        float v[HD];
        const float* row = g_attn_r + (bh * HD + t) * HD;
        float mx = -1e30f;
        const float inq = temp / nq[t];
#pragma unroll 8
        for (int e = 0; e < HD; e++) {
            v[e] = row[e] * inq / nk[e];
            mx = fmaxf(mx, v[e]);
        }
        float ssum = 0.f;
#pragma unroll 8
        for (int e = 0; e < HD; e++) { v[e] = __expf(v[e] - mx); ssum += v[e]; }
        const float inv = 1.f / ssum;
        float* orow = g_attn_s + (bh * HD + t) * HD;
#pragma unroll 8
        for (int e = 0; e < HD; e++) orow[e] = v[e] * inv;
    }
}

// ---------------------------------------------------------------
__global__ void w2_kernel(const float* __restrict__ w_proj)
{
    const int bo = blockIdx.x;
    const int b = bo / CDIM, o = bo % CDIM;
    const int he = threadIdx.x;
    const int h = he / HD, e = he % HD;
    const float* wp = w_proj + o * CDIM + h * HD;
    const float* at = g_attn_s + ((long)(b * NH + h) * HD) * HD + e;
    float s = 0.f;
#pragma unroll 8
    for (int d = 0; d < HD; d++) s = fmaf(wp[d], at[d * HD], s);
    g_W2[((long)b * CDIM + o) * CDIM + he] = cvt_tf32(s);
}

// ---------------------------------------------------------------
extern "C" void kernel_launch(void* const* d_in, const int* in_sizes, int n_in,
                              void* d_out, int out_size)
{
    const float* x      = (const float*)d_in[0];
    const float* w_qkv  = (const float*)d_in[1];
    const float* w_dw   = (const float*)d_in[2];
    const float* w_proj = (const float*)d_in[3];
    const float* ltemp  = (const float*)d_in[4];
    float* out = (float*)d_out;

    float *p_qkv, *p_dw, *p_xt, *p_wqt, *p_W2;
    cudaGetSymbolAddress((void**)&p_qkv, g_qkv);
    cudaGetSymbolAddress((void**)&p_dw,  g_dw);
    cudaGetSymbolAddress((void**)&p_xt,  g_xt);
    cudaGetSymbolAddress((void**)&p_wqt, g_wqt);
    cudaGetSymbolAddress((void**)&p_W2,  g_W2);

    static int smem_set = 0;
    if (!smem_set) {
        cudaFuncSetAttribute(tf32_gemm_kernel,
                             cudaFuncAttributeMaxDynamicSharedMemorySize,
                             GEMM_SMEM_BYTES);
        cudaFuncSetAttribute(attn_kernel,
                             cudaFuncAttributeMaxDynamicSharedMemorySize,
                             ATTN_SMEM_BYTES);
        smem_set = 1;
    }

    // tf32 pre-round + sumsq zeroing (fused)
    cvt_kernel<<<1184, 256>>>((const float4*)x, (const float4*)w_qkv);

    // GEMM1: qkv = w_qkv @ x
    tf32_gemm_kernel<<<dim3(HWSZ / 256, OC3 / 64, BATCH), 256, GEMM_SMEM_BYTES>>>(
        p_wqt, p_xt, p_qkv, 0L, (long)CDIM * HWSZ, (long)OC3 * HWSZ);

    // depthwise 3x3 + q/k sum-of-squares (R9 layout)
    dw_kernel<<<dim3(3, 3, BATCH * OC3), 256>>>(w_dw);

    // attn partials (tensor cores, split-tf32, smem-staged coalesced loads)
    attn_kernel<<<dim3(ACH, BATCH * NH), 256, ATTN_SMEM_BYTES>>>();

    // parallel reduce, then normalize + temperature + softmax
    reduce_kernel<<<dim3(HD * HD / 256, BATCH * NH), 256>>>();
    softmax_kernel<<<BATCH * NH, 64>>>(ltemp);
    w2_kernel<<<BATCH * CDIM, 192>>>(w_proj);

    // GEMM2: out = W2[b] @ v[b]
    tf32_gemm_kernel<<<dim3(HWSZ / 256, CDIM / 64, BATCH), 256, GEMM_SMEM_BYTES>>>(
        p_W2, p_dw + (long)2 * CDIM * HWSZ, out,
        (long)CDIM * CDIM, (long)OC3 * HWSZ, (long)CDIM * HWSZ);
}

// round 13
// speedup vs baseline: 1.1451x; 1.1451x over previous
#include <cuda_runtime.h>
#include <math.h>
#include <stdint.h>

#define BATCH 2
#define CDIM 192
#define HH 192
#define WW 192
#define HWSZ (HH*WW)      // 36864
#define OC3 (3*CDIM)      // 576
#define NH 4
#define HD 48
#define ACH 36            // attn chunks per (b,h): 1024 cols each

#define ASTRIDE 36        // As row stride (floats)
#define BSTRIDE 264       // Bs row stride (floats)
#define STAGE_FLOATS (64*ASTRIDE + 32*BSTRIDE)   // 10752
#define GEMM_SMEM_BYTES (2 * STAGE_FLOATS * 4)   // 86016

// ---- scratch (device globals; no allocations allowed) ----
__device__ float g_qkv[(long)BATCH*OC3*HWSZ];   // after 1x1 conv
__device__ float g_dw [(long)BATCH*OC3*HWSZ];   // after depthwise conv
__device__ float g_xt [(long)BATCH*CDIM*HWSZ];  // x pre-rounded to tf32
__device__ float g_wqt[OC3*CDIM];                // w_qkv pre-rounded to tf32
__device__ float g_sumsq[BATCH*2*CDIM];          // per-channel sum of squares (q,k)
__device__ float g_attn_part[(long)BATCH*NH*ACH*HD*HD]; // per-chunk partial q.k^T
__device__ float g_attn_r[BATCH*NH*HD*HD];       // reduced raw attn
__device__ float g_attn_s[BATCH*NH*HD*HD];       // softmaxed
__device__ float g_W2[BATCH*CDIM*CDIM];          // w_proj @ blockdiag(attn), tf32-rounded

__device__ __forceinline__ float cvt_tf32(float x) {
    unsigned u;
    asm("cvt.rna.tf32.f32 %0, %1;" : "=r"(u) : "f"(x));
    return __uint_as_float(u);
}
__device__ __forceinline__ void cp_async16(uint32_t dst, const void* src) {
    asm volatile("cp.async.cg.shared.global [%0], [%1], 16;" :: "r"(dst), "l"(src));
}
__device__ __forceinline__ void cp_commit() {
    asm volatile("cp.async.commit_group;");
}
template <int N>
__device__ __forceinline__ void cp_wait() {
    asm volatile("cp.async.wait_group %0;" :: "n"(N));
}

// ---------------------------------------------------------------
// pre-round x and w_qkv to tf32 (RNA); also zero sumsq accumulators.
// ---------------------------------------------------------------
__global__ __launch_bounds__(256) void cvt_kernel(
    const float4* __restrict__ x, const float4* __restrict__ wq)
{
    const long NX = (long)BATCH*CDIM*HWSZ/4;
    float4* xt = (float4*)g_xt;
    float4* wt = (float4*)g_wqt;
    long i0 = (long)blockIdx.x * blockDim.x + threadIdx.x;
    if (i0 < BATCH*2*CDIM) g_sumsq[i0] = 0.f;
    for (long i = i0; i < NX; i += (long)gridDim.x * blockDim.x) {
        float4 v = x[i];
        v.x = cvt_tf32(v.x); v.y = cvt_tf32(v.y);
        v.z = cvt_tf32(v.z); v.w = cvt_tf32(v.w);
        xt[i] = v;
    }
    if (i0 < OC3*CDIM/4) {
        float4 v = wq[i0];
        v.x = cvt_tf32(v.x); v.y = cvt_tf32(v.y);
        v.z = cvt_tf32(v.z); v.w = cvt_tf32(v.w);
        wt[i0] = v;
    }
}

// ---------------------------------------------------------------
// TF32 tensor-core GEMM, cp.async double-buffered, 64x256xBK32.
// ---------------------------------------------------------------
__global__ __launch_bounds__(256, 2) void tf32_gemm_kernel(
    const float* __restrict__ A, const float* __restrict__ Bm, float* __restrict__ Cm,
    long aStride, long bStride, long cStride)
{
    extern __shared__ float smem_[];

    const int t = threadIdx.x;
    const float* Ab = A  + (long)blockIdx.z * aStride + (long)blockIdx.y * 64 * 192;
    const float* Bb = Bm + (long)blockIdx.z * bStride + blockIdx.x * 256;
    float*       Cb = Cm + (long)blockIdx.z * cStride;

    const int arow0 = t >> 3,          akq0 = t & 7;
    const int arow1 = (t + 256) >> 3,  akq1 = t & 7;
    const int bk = t >> 5;
    const int bc = (t & 31);

    const int w = t >> 5, l = t & 31;
    const int mw = (w >> 2) * 32;
    const int nw = (w & 3) * 64;
    const int g = l >> 2, q_ = l & 3;

    uint32_t smem_u = (uint32_t)__cvta_generic_to_shared(smem_);

    float acc[2][8][4];
#pragma unroll
    for (int mt = 0; mt < 2; mt++)
#pragma unroll
        for (int nt = 0; nt < 8; nt++)
#pragma unroll
            for (int c = 0; c < 4; c++) acc[mt][nt][c] = 0.f;

    auto load_stage = [&](int stage, int k0) {
        uint32_t As_u = smem_u + stage * STAGE_FLOATS * 4;
        uint32_t Bs_u = As_u + 64 * ASTRIDE * 4;
        cp_async16(As_u + (arow0 * ASTRIDE + akq0 * 4) * 4,
                   Ab + (long)arow0 * 192 + k0 + akq0 * 4);
        cp_async16(As_u + (arow1 * ASTRIDE + akq1 * 4) * 4,
                   Ab + (long)arow1 * 192 + k0 + akq1 * 4);
#pragma unroll
        for (int r = 0; r < 4; r++) {
            const int krow = bk + r * 8;
            const float* src = Bb + (long)(k0 + krow) * HWSZ;
            uint32_t drow = Bs_u + krow * BSTRIDE * 4;
            cp_async16(drow + bc * 16,        src + bc * 4);
            cp_async16(drow + (bc + 32) * 16, src + (bc + 32) * 4);
        }
        cp_commit();
    };

    load_stage(0, 0);

    for (int kt = 0; kt < 6; kt++) {
        if (kt < 5) load_stage((kt + 1) & 1, (kt + 1) * 32);
        if (kt < 5) cp_wait<1>(); else cp_wait<0>();
        __syncthreads();

        const float* As = smem_ + (kt & 1) * STAGE_FLOATS;
        const float* Bs = As + 64 * ASTRIDE;

#pragma unroll
        for (int s = 0; s < 4; s++) {
            const int kb = s * 8;
            unsigned a[2][4], bf[8][2];
#pragma unroll
            for (int mt = 0; mt < 2; mt++) {
                const float* ar = As + (mw + mt * 16 + g) * ASTRIDE + kb;
                a[mt][0] = __float_as_uint(ar[q_]);
                a[mt][1] = __float_as_uint(ar[8 * ASTRIDE + q_]);
                a[mt][2] = __float_as_uint(ar[q_ + 4]);
                a[mt][3] = __float_as_uint(ar[8 * ASTRIDE + q_ + 4]);
            }
#pragma unroll
            for (int nt = 0; nt < 8; nt++) {
                bf[nt][0] = __float_as_uint(Bs[(kb + q_) * BSTRIDE + nw + nt * 8 + g]);
                bf[nt][1] = __float_as_uint(Bs[(kb + q_ + 4) * BSTRIDE + nw + nt * 8 + g]);
            }
#pragma unroll
            for (int mt = 0; mt < 2; mt++)
#pragma unroll
                for (int nt = 0; nt < 8; nt++) {
                    float* d = acc[mt][nt];
                    asm volatile(
                        "mma.sync.aligned.m16n8k8.row.col.f32.tf32.tf32.f32 "
                        "{%0,%1,%2,%3}, {%4,%5,%6,%7}, {%8,%9}, {%0,%1,%2,%3};\n"
                        : "+f"(d[0]), "+f"(d[1]), "+f"(d[2]), "+f"(d[3])
                        : "r"(a[mt][0]), "r"(a[mt][1]), "r"(a[mt][2]), "r"(a[mt][3]),
                          "r"(bf[nt][0]), "r"(bf[nt][1]));
                }
        }
        __syncthreads();
    }

    const int colb = blockIdx.x * 256 + nw;
    const int rowb = blockIdx.y * 64 + mw;
#pragma unroll
    for (int mt = 0; mt < 2; mt++)
#pragma unroll
        for (int nt = 0; nt < 8; nt++) {
            const int row = rowb + mt * 16 + g;
            const int col = colb + nt * 8 + 2 * q_;
            *(float2*)(Cb + (long)row * HWSZ + col) =
                make_float2(acc[mt][nt][0], acc[mt][nt][1]);
            *(float2*)(Cb + (long)(row + 8) * HWSZ + col) =
                make_float2(acc[mt][nt][2], acc[mt][nt][3]);
        }
}

// ---------------------------------------------------------------
// Depthwise 3x3 SAME, 64x64 tile, 16 outputs/thread. (R9 version)
// grid: (3, 3, BATCH*576), block 256
// ---------------------------------------------------------------
__global__ __launch_bounds__(256) void dw_kernel(const float* __restrict__ wdw)
{
    const int bc = blockIdx.z;
    const int c  = bc % OC3;
    const int b  = bc / OC3;
    const float* __restrict__ p = g_qkv + (long)bc * HWSZ;
    float*       __restrict__ o = g_dw  + (long)bc * HWSZ;

    __shared__ float tile[66][68];     // interior at [1..64][1..64]
    const int x0 = blockIdx.x * 64, y0 = blockIdx.y * 64;
    const int tid = threadIdx.x;

    // interior 64x64: 4 float4 loads per thread, zero predicates
    {
        const int col  = (tid & 15) * 4;
        const int row0 = tid >> 4;
#pragma unroll
        for (int rr = 0; rr < 4; rr++) {
            const int row = row0 + rr * 16;
            float4 v = *(const float4*)(p + (long)(y0 + row) * WW + x0 + col);
            tile[row + 1][col + 1] = v.x;
            tile[row + 1][col + 2] = v.y;
            tile[row + 1][col + 3] = v.z;
            tile[row + 1][col + 4] = v.w;
        }
    }
    // halo strips: 4 x 64 elements
    {
        const int qd = tid >> 6, i = tid & 63;
        int gy, gx; float* dst;
        if (qd == 0)      { gy = y0 - 1;  gx = x0 + i;  dst = &tile[0][i + 1]; }
        else if (qd == 1) { gy = y0 + 64; gx = x0 + i;  dst = &tile[65][i + 1]; }
        else if (qd == 2) { gy = y0 + i;  gx = x0 - 1;  dst = &tile[i + 1][0]; }
        else              { gy = y0 + i;  gx = x0 + 64; dst = &tile[i + 1][65]; }
        *dst = (gy >= 0 && gy < HH && gx >= 0 && gx < WW) ? p[gy * WW + gx] : 0.f;
    }
    // corners
    if (tid < 4) {
        const int cy = (tid & 1) ? 65 : 0;
        const int cx = (tid & 2) ? 65 : 0;
        const int gy = y0 + ((tid & 1) ? 64 : -1);
        const int gx = x0 + ((tid & 2) ? 64 : -1);
        tile[cy][cx] = (gy >= 0 && gy < HH && gx >= 0 && gx < WW)
                           ? p[gy * WW + gx] : 0.f;
    }
    __syncthreads();

    float wv[9];
#pragma unroll
    for (int i = 0; i < 9; i++) wv[i] = __ldg(&wdw[c * 9 + i]);

    const int tx = (tid & 15) * 4;
    const int ty = (tid >> 4) * 4;
    const bool isqk = (c < 2 * CDIM);

    float ssq = 0.f;
#pragma unroll
    for (int i = 0; i < 4; i++) {
        float r0[6], r1[6], r2[6];
#pragma unroll
        for (int j = 0; j < 6; j++) {
            r0[j] = tile[ty + i    ][tx + j];
            r1[j] = tile[ty + i + 1][tx + j];
            r2[j] = tile[ty + i + 2][tx + j];
        }
        float4 ov;
        float* op = (float*)&ov;
#pragma unroll
        for (int j = 0; j < 4; j++) {
            float s = 0.f;
            s = fmaf(wv[0], r0[j],     s);
            s = fmaf(wv[1], r0[j + 1], s);
            s = fmaf(wv[2], r0[j + 2], s);
            s = fmaf(wv[3], r1[j],     s);
            s = fmaf(wv[4], r1[j + 1], s);
            s = fmaf(wv[5], r1[j + 2], s);
            s = fmaf(wv[6], r2[j],     s);
            s = fmaf(wv[7], r2[j + 1], s);
            s = fmaf(wv[8], r2[j + 2], s);
            ssq = fmaf(s, s, ssq);
            op[j] = isqk ? s : cvt_tf32(s);
        }
        *(float4*)(o + (long)(y0 + ty + i) * WW + x0 + tx) = ov;
    }

    if (isqk) {
#pragma unroll
        for (int off = 16; off > 0; off >>= 1)
            ssq += __shfl_xor_sync(0xffffffffu, ssq, off);
        __shared__ float wsum[8];
        const int lane = tid & 31, wrp = tid >> 5;
        if (lane == 0) wsum[wrp] = ssq;
        __syncthreads();
        if (tid == 0) {
            float tot = 0.f;
#pragma unroll
            for (int i = 0; i < 8; i++) tot += wsum[i];
            atomicAdd(&g_sumsq[b * 2 * CDIM + c], tot);
        }
    }
}

// ---------------------------------------------------------------
// attn partials via tensor cores, split-tf32, direct GMEM fragment
// loads (proven 52us version), chunk = 1024 cols -> grid 288 =
// exactly one wave at 2 blocks/SM.
// grid: (ACH=36, BATCH*NH), block 256
// ---------------------------------------------------------------
__global__ __launch_bounds__(256, 2) void attn_kernel()
{
    const int bh = blockIdx.y;
    const int b = bh >> 2, h = bh & 3;
    const float* __restrict__ qbase = g_dw + ((long)b * OC3 + h * HD) * HWSZ;
    const float* __restrict__ kbase = g_dw + ((long)b * OC3 + CDIM + h * HD) * HWSZ;

    const int t = threadIdx.x;
    const int w = t >> 5, l = t & 31;
    const int g = l >> 2, q_ = l & 3;
    const int n0 = blockIdx.x * 1024 + w * 128;

    __shared__ float buf[HD * HD];
    for (int i = t; i < HD * HD; i += 256) buf[i] = 0.f;
    __syncthreads();

    float acc[3][6][4];
#pragma unroll
    for (int mt = 0; mt < 3; mt++)
#pragma unroll
        for (int nt = 0; nt < 6; nt++)
#pragma unroll
            for (int c = 0; c < 4; c++) acc[mt][nt][c] = 0.f;

    for (int ks = 0; ks < 16; ks++) {
        const int nn = n0 + ks * 8;
        unsigned ah[3][4], al[3][4], bhx[6][2], blx[6][2];
#pragma unroll
        for (int mt = 0; mt < 3; mt++) {
            const float* p0 = qbase + (long)(mt * 16 + g) * HWSZ + nn + q_;
            const float* p1 = p0 + 8 * HWSZ;
            float v0 = p0[0], v1 = p1[0], v2 = p0[4], v3 = p1[4];
            float h0 = cvt_tf32(v0), h1 = cvt_tf32(v1);
            float h2 = cvt_tf32(v2), h3 = cvt_tf32(v3);
            ah[mt][0] = __float_as_uint(h0); al[mt][0] = __float_as_uint(cvt_tf32(v0 - h0));
            ah[mt][1] = __float_as_uint(h1); al[mt][1] = __float_as_uint(cvt_tf32(v1 - h1));
            ah[mt][2] = __float_as_uint(h2); al[mt][2] = __float_as_uint(cvt_tf32(v2 - h2));
            ah[mt][3] = __float_as_uint(h3); al[mt][3] = __float_as_uint(cvt_tf32(v3 - h3));
        }
#pragma unroll
        for (int nt = 0; nt < 6; nt++) {
            const float* p = kbase + (long)(nt * 8 + g) * HWSZ + nn + q_;
            float v0 = p[0], v1 = p[4];
            float h0 = cvt_tf32(v0), h1 = cvt_tf32(v1);
            bhx[nt][0] = __float_as_uint(h0); blx[nt][0] = __float_as_uint(cvt_tf32(v0 - h0));
            bhx[nt][1] = __float_as_uint(h1); blx[nt][1] = __float_as_uint(cvt_tf32(v1 - h1));
        }
#pragma unroll
        for (int mt = 0; mt < 3; mt++)
#pragma unroll
            for (int nt = 0; nt < 6; nt++) {
                float* d = acc[mt][nt];
                asm volatile(
                    "mma.sync.aligned.m16n8k8.row.col.f32.tf32.tf32.f32 "
                    "{%0,%1,%2,%3}, {%4,%5,%6,%7}, {%8,%9}, {%0,%1,%2,%3};\n"
                    : "+f"(d[0]), "+f"(d[1]), "+f"(d[2]), "+f"(d[3])
                    : "r"(ah[mt][0]), "r"(ah[mt][1]), "r"(ah[mt][2]), "r"(ah[mt][3]),
                      "r"(bhx[nt][0]), "r"(bhx[nt][1]));
                asm volatile(
                    "mma.sync.aligned.m16n8k8.row.col.f32.tf32.tf32.f32 "
                    "{%0,%1,%2,%3}, {%4,%5,%6,%7}, {%8,%9}, {%0,%1,%2,%3};\n"
                    : "+f"(d[0]), "+f"(d[1]), "+f"(d[2]), "+f"(d[3])
                    : "r"(al[mt][0]), "r"(al[mt][1]), "r"(al[mt][2]), "r"(al[mt][3]),
                      "r"(bhx[nt][0]), "r"(bhx[nt][1]));
                asm volatile(
                    "mma.sync.aligned.m16n8k8.row.col.f32.tf32.tf32.f32 "
                    "{%0,%1,%2,%3}, {%4,%5,%6,%7}, {%8,%9}, {%0,%1,%2,%3};\n"
                    : "+f"(d[0]), "+f"(d[1]), "+f"(d[2]), "+f"(d[3])
                    : "r"(ah[mt][0]), "r"(ah[mt][1]), "r"(ah[mt][2]), "r"(ah[mt][3]),
                      "r"(blx[nt][0]), "r"(blx[nt][1]));
            }
    }

#pragma unroll
    for (int mt = 0; mt < 3; mt++)
#pragma unroll
        for (int nt = 0; nt < 6; nt++) {
            const int r0 = mt * 16 + g, c0 = nt * 8 + 2 * q_;
            atomicAdd(&buf[r0 * HD + c0],       acc[mt][nt][0]);
            atomicAdd(&buf[r0 * HD + c0 + 1],   acc[mt][nt][1]);
            atomicAdd(&buf[(r0+8) * HD + c0],   acc[mt][nt][2]);
            atomicAdd(&buf[(r0+8) * HD + c0+1], acc[mt][nt][3]);
        }
    __syncthreads();

    float* op = g_attn_part + ((long)bh * ACH + blockIdx.x) * HD * HD;
    for (int i = t; i < HD * HD; i += 256) op[i] = buf[i];
}

// ---------------------------------------------------------------
// parallel reduce of the ACH partials: grid (9, 8), 256 threads.
// ---------------------------------------------------------------
__global__ __launch_bounds__(256) void reduce_kernel()
{
    const int bh = blockIdx.y;
    const int cell = blockIdx.x * 256 + threadIdx.x;
    const float* pp = g_attn_part + (long)bh * ACH * HD * HD + cell;
    float s = 0.f;
#pragma unroll 6
    for (int c = 0; c < ACH; c++) s += pp[(long)c * HD * HD];
    g_attn_r[bh * HD * HD + cell] = s;
}

// ---------------------------------------------------------------
__global__ void softmax_kernel(const float* __restrict__ log_temp)
{
    const int bh = blockIdx.x;
    const int b = bh >> 2, h = bh & 3;
    __shared__ float nq[HD], nk[HD];
    const int t = threadIdx.x;
    if (t < HD) {
        nq[t] = fmaxf(sqrtf(g_sumsq[b * 2 * CDIM + h * HD + t]), 1e-12f);
        nk[t] = fmaxf(sqrtf(g_sumsq[b * 2 * CDIM + CDIM + h * HD + t]), 1e-12f);
    }
    __syncthreads();
    const float temp = log1pf(expf(log_temp[h])) + 1e-6f;
    if (t < HD) {
        float v[HD];
        const float* row = g_attn_r + (bh * HD + t) * HD;
        float mx = -1e30f;
        const float inq = temp / nq[t];
#pragma unroll 8
        for (int e = 0; e < HD; e++) {
            v[e] = row[e] * inq / nk[e];
            mx = fmaxf(mx, v[e]);
        }
        float ssum = 0.f;
#pragma unroll 8
        for (int e = 0; e < HD; e++) { v[e] = __expf(v[e] - mx); ssum += v[e]; }
        const float inv = 1.f / ssum;
        float* orow = g_attn_s + (bh * HD + t) * HD;
#pragma unroll 8
        for (int e = 0; e < HD; e++) orow[e] = v[e] * inv;
    }
}

// ---------------------------------------------------------------
__global__ void w2_kernel(const float* __restrict__ w_proj)
{
    const int bo = blockIdx.x;
    const int b = bo / CDIM, o = bo % CDIM;
    const int he = threadIdx.x;
    const int h = he / HD, e = he % HD;
    const float* wp = w_proj + o * CDIM + h * HD;
    const float* at = g_attn_s + ((long)(b * NH + h) * HD) * HD + e;
    float s = 0.f;
#pragma unroll 8
    for (int d = 0; d < HD; d++) s = fmaf(wp[d], at[d * HD], s);
    g_W2[((long)b * CDIM + o) * CDIM + he] = cvt_tf32(s);
}

// ---------------------------------------------------------------
extern "C" void kernel_launch(void* const* d_in, const int* in_sizes, int n_in,
                              void* d_out, int out_size)
{
    const float* x      = (const float*)d_in[0];
    const float* w_qkv  = (const float*)d_in[1];
    const float* w_dw   = (const float*)d_in[2];
    const float* w_proj = (const float*)d_in[3];
    const float* ltemp  = (const float*)d_in[4];
    float* out = (float*)d_out;

    float *p_qkv, *p_dw, *p_xt, *p_wqt, *p_W2;
    cudaGetSymbolAddress((void**)&p_qkv, g_qkv);
    cudaGetSymbolAddress((void**)&p_dw,  g_dw);
    cudaGetSymbolAddress((void**)&p_xt,  g_xt);
    cudaGetSymbolAddress((void**)&p_wqt, g_wqt);
    cudaGetSymbolAddress((void**)&p_W2,  g_W2);

    static int smem_set = 0;
    if (!smem_set) {
        cudaFuncSetAttribute(tf32_gemm_kernel,
                             cudaFuncAttributeMaxDynamicSharedMemorySize,
                             GEMM_SMEM_BYTES);
        smem_set = 1;
    }

    // tf32 pre-round + sumsq zeroing (fused)
    cvt_kernel<<<1184, 256>>>((const float4*)x, (const float4*)w_qkv);

    // GEMM1: qkv = w_qkv @ x
    tf32_gemm_kernel<<<dim3(HWSZ / 256, OC3 / 64, BATCH), 256, GEMM_SMEM_BYTES>>>(
        p_wqt, p_xt, p_qkv, 0L, (long)CDIM * HWSZ, (long)OC3 * HWSZ);

    // depthwise 3x3 + q/k sum-of-squares (R9 layout)
    dw_kernel<<<dim3(3, 3, BATCH * OC3), 256>>>(w_dw);

    // attn partials (direct-GMEM tensor cores, split-tf32, 1 wave)
    attn_kernel<<<dim3(ACH, BATCH * NH), 256>>>();

    // parallel reduce, then normalize + temperature + softmax
    reduce_kernel<<<dim3(HD * HD / 256, BATCH * NH), 256>>>();
    softmax_kernel<<<BATCH * NH, 64>>>(ltemp);
    w2_kernel<<<BATCH * CDIM, 192>>>(w_proj);

    // GEMM2: out = W2[b] @ v[b]
    tf32_gemm_kernel<<<dim3(HWSZ / 256, CDIM / 64, BATCH), 256, GEMM_SMEM_BYTES>>>(
        p_W2, p_dw + (long)2 * CDIM * HWSZ, out,
        (long)CDIM * CDIM, (long)OC3 * HWSZ, (long)CDIM * HWSZ);
}

// round 14
// speedup vs baseline: 1.1884x; 1.0378x over previous
#include <cuda_runtime.h>
#include <math.h>
#include <stdint.h>

#define BATCH 2
#define CDIM 192
#define HH 192
#define WW 192
#define HWSZ (HH*WW)      // 36864
#define OC3 (3*CDIM)      // 576
#define NH 4
#define HD 48
#define ACH 36            // attn chunks per (b,h): 1024 cols each

#define ASTRIDE 36        // As row stride (floats)
#define BSTRIDE 264       // Bs row stride (floats)
#define STAGE_FLOATS (64*ASTRIDE + 32*BSTRIDE)   // 10752
#define GEMM_SMEM_BYTES (2 * STAGE_FLOATS * 4)   // 86016

// ---- scratch (device globals; no allocations allowed) ----
__device__ float g_qkv[(long)BATCH*OC3*HWSZ];   // after 1x1 conv
__device__ float g_dw [(long)BATCH*OC3*HWSZ];   // after depthwise conv
__device__ float g_sumsq[BATCH*2*CDIM];          // per-channel sum of squares (q,k)
__device__ float g_attn_part[(long)BATCH*NH*ACH*HD*HD]; // per-chunk partial q.k^T
__device__ float g_attn_r[BATCH*NH*HD*HD];       // reduced raw attn
__device__ float g_attn_s[BATCH*NH*HD*HD];       // softmaxed
__device__ float g_W2[BATCH*CDIM*CDIM];          // w_proj @ blockdiag(attn), tf32-rounded

__device__ __forceinline__ float cvt_tf32(float x) {
    unsigned u;
    asm("cvt.rna.tf32.f32 %0, %1;" : "=r"(u) : "f"(x));
    return __uint_as_float(u);
}
__device__ __forceinline__ void cp_async16(uint32_t dst, const void* src) {
    asm volatile("cp.async.cg.shared.global [%0], [%1], 16;" :: "r"(dst), "l"(src));
}
__device__ __forceinline__ void cp_commit() {
    asm volatile("cp.async.commit_group;");
}
template <int N>
__device__ __forceinline__ void cp_wait() {
    asm volatile("cp.async.wait_group %0;" :: "n"(N));
}

// ---------------------------------------------------------------
// zero sumsq accumulators (graph replays need this each call)
// ---------------------------------------------------------------
__global__ void zero_kernel() {
    int i = blockIdx.x * blockDim.x + threadIdx.x;
    if (i < BATCH*2*CDIM) g_sumsq[i] = 0.f;
}

// ---------------------------------------------------------------
// TF32 tensor-core GEMM, cp.async double-buffered, 64x256xBK32.
// CVT: apply cvt.rna at fragment-load time (raw fp32 operands);
// bit-identical to pre-rounding the operands.
// ---------------------------------------------------------------
template <bool CVT>
__global__ __launch_bounds__(256, 2) void tf32_gemm_kernel(
    const float* __restrict__ A, const float* __restrict__ Bm, float* __restrict__ Cm,
    long aStride, long bStride, long cStride)
{
    extern __shared__ float smem_[];

    const int t = threadIdx.x;
    const float* Ab = A  + (long)blockIdx.z * aStride + (long)blockIdx.y * 64 * 192;
    const float* Bb = Bm + (long)blockIdx.z * bStride + blockIdx.x * 256;
    float*       Cb = Cm + (long)blockIdx.z * cStride;

    const int arow0 = t >> 3,          akq0 = t & 7;
    const int arow1 = (t + 256) >> 3,  akq1 = t & 7;
    const int bk = t >> 5;
    const int bc = (t & 31);

    const int w = t >> 5, l = t & 31;
    const int mw = (w >> 2) * 32;
    const int nw = (w & 3) * 64;
    const int g = l >> 2, q_ = l & 3;

    uint32_t smem_u = (uint32_t)__cvta_generic_to_shared(smem_);

    float acc[2][8][4];
#pragma unroll
    for (int mt = 0; mt < 2; mt++)
#pragma unroll
        for (int nt = 0; nt < 8; nt++)
#pragma unroll
            for (int c = 0; c < 4; c++) acc[mt][nt][c] = 0.f;

    auto load_stage = [&](int stage, int k0) {
        uint32_t As_u = smem_u + stage * STAGE_FLOATS * 4;
        uint32_t Bs_u = As_u + 64 * ASTRIDE * 4;
        cp_async16(As_u + (arow0 * ASTRIDE + akq0 * 4) * 4,
                   Ab + (long)arow0 * 192 + k0 + akq0 * 4);
        cp_async16(As_u + (arow1 * ASTRIDE + akq1 * 4) * 4,
                   Ab + (long)arow1 * 192 + k0 + akq1 * 4);
#pragma unroll
        for (int r = 0; r < 4; r++) {
            const int krow = bk + r * 8;
            const float* src = Bb + (long)(k0 + krow) * HWSZ;
            uint32_t drow = Bs_u + krow * BSTRIDE * 4;
            cp_async16(drow + bc * 16,        src + bc * 4);
            cp_async16(drow + (bc + 32) * 16, src + (bc + 32) * 4);
        }
        cp_commit();
    };

    load_stage(0, 0);

    for (int kt = 0; kt < 6; kt++) {
        if (kt < 5) load_stage((kt + 1) & 1, (kt + 1) * 32);
        if (kt < 5) cp_wait<1>(); else cp_wait<0>();
        __syncthreads();

        const float* As = smem_ + (kt & 1) * STAGE_FLOATS;
        const float* Bs = As + 64 * ASTRIDE;

#pragma unroll
        for (int s = 0; s < 4; s++) {
            const int kb = s * 8;
            unsigned a[2][4], bf[8][2];
#pragma unroll
            for (int mt = 0; mt < 2; mt++) {
                const float* ar = As + (mw + mt * 16 + g) * ASTRIDE + kb;
                float a0 = ar[q_];
                float a1 = ar[8 * ASTRIDE + q_];
                float a2 = ar[q_ + 4];
                float a3 = ar[8 * ASTRIDE + q_ + 4];
                if (CVT) { a0 = cvt_tf32(a0); a1 = cvt_tf32(a1);
                           a2 = cvt_tf32(a2); a3 = cvt_tf32(a3); }
                a[mt][0] = __float_as_uint(a0);
                a[mt][1] = __float_as_uint(a1);
                a[mt][2] = __float_as_uint(a2);
                a[mt][3] = __float_as_uint(a3);
            }
#pragma unroll
            for (int nt = 0; nt < 8; nt++) {
                float b0 = Bs[(kb + q_) * BSTRIDE + nw + nt * 8 + g];
                float b1 = Bs[(kb + q_ + 4) * BSTRIDE + nw + nt * 8 + g];
                if (CVT) { b0 = cvt_tf32(b0); b1 = cvt_tf32(b1); }
                bf[nt][0] = __float_as_uint(b0);
                bf[nt][1] = __float_as_uint(b1);
            }
#pragma unroll
            for (int mt = 0; mt < 2; mt++)
#pragma unroll
                for (int nt = 0; nt < 8; nt++) {
                    float* d = acc[mt][nt];
                    asm volatile(
                        "mma.sync.aligned.m16n8k8.row.col.f32.tf32.tf32.f32 "
                        "{%0,%1,%2,%3}, {%4,%5,%6,%7}, {%8,%9}, {%0,%1,%2,%3};\n"
                        : "+f"(d[0]), "+f"(d[1]), "+f"(d[2]), "+f"(d[3])
                        : "r"(a[mt][0]), "r"(a[mt][1]), "r"(a[mt][2]), "r"(a[mt][3]),
                          "r"(bf[nt][0]), "r"(bf[nt][1]));
                }
        }
        __syncthreads();
    }

    const int colb = blockIdx.x * 256 + nw;
    const int rowb = blockIdx.y * 64 + mw;
#pragma unroll
    for (int mt = 0; mt < 2; mt++)
#pragma unroll
        for (int nt = 0; nt < 8; nt++) {
            const int row = rowb + mt * 16 + g;
            const int col = colb + nt * 8 + 2 * q_;
            *(float2*)(Cb + (long)row * HWSZ + col) =
                make_float2(acc[mt][nt][0], acc[mt][nt][1]);
            *(float2*)(Cb + (long)(row + 8) * HWSZ + col) =
                make_float2(acc[mt][nt][2], acc[mt][nt][3]);
        }
}

// ---------------------------------------------------------------
// Depthwise 3x3 SAME, 64x64 tile, 16 outputs/thread. (R9 version)
// grid: (3, 3, BATCH*576), block 256
// ---------------------------------------------------------------
__global__ __launch_bounds__(256) void dw_kernel(const float* __restrict__ wdw)
{
    const int bc = blockIdx.z;
    const int c  = bc % OC3;
    const int b  = bc / OC3;
    const float* __restrict__ p = g_qkv + (long)bc * HWSZ;
    float*       __restrict__ o = g_dw  + (long)bc * HWSZ;

    __shared__ float tile[66][68];     // interior at [1..64][1..64]
    const int x0 = blockIdx.x * 64, y0 = blockIdx.y * 64;
    const int tid = threadIdx.x;

    // interior 64x64: 4 float4 loads per thread, zero predicates
    {
        const int col  = (tid & 15) * 4;
        const int row0 = tid >> 4;
#pragma unroll
        for (int rr = 0; rr < 4; rr++) {
            const int row = row0 + rr * 16;
            float4 v = *(const float4*)(p + (long)(y0 + row) * WW + x0 + col);
            tile[row + 1][col + 1] = v.x;
            tile[row + 1][col + 2] = v.y;
            tile[row + 1][col + 3] = v.z;
            tile[row + 1][col + 4] = v.w;
        }
    }
    // halo strips: 4 x 64 elements
    {
        const int qd = tid >> 6, i = tid & 63;
        int gy, gx; float* dst;
        if (qd == 0)      { gy = y0 - 1;  gx = x0 + i;  dst = &tile[0][i + 1]; }
        else if (qd == 1) { gy = y0 + 64; gx = x0 + i;  dst = &tile[65][i + 1]; }
        else if (qd == 2) { gy = y0 + i;  gx = x0 - 1;  dst = &tile[i + 1][0]; }
        else              { gy = y0 + i;  gx = x0 + 64; dst = &tile[i + 1][65]; }
        *dst = (gy >= 0 && gy < HH && gx >= 0 && gx < WW) ? p[gy * WW + gx] : 0.f;
    }
    // corners
    if (tid < 4) {
        const int cy = (tid & 1) ? 65 : 0;
        const int cx = (tid & 2) ? 65 : 0;
        const int gy = y0 + ((tid & 1) ? 64 : -1);
        const int gx = x0 + ((tid & 2) ? 64 : -1);
        tile[cy][cx] = (gy >= 0 && gy < HH && gx >= 0 && gx < WW)
                           ? p[gy * WW + gx] : 0.f;
    }
    __syncthreads();

    float wv[9];
#pragma unroll
    for (int i = 0; i < 9; i++) wv[i] = __ldg(&wdw[c * 9 + i]);

    const int tx = (tid & 15) * 4;
    const int ty = (tid >> 4) * 4;
    const bool isqk = (c < 2 * CDIM);

    float ssq = 0.f;
#pragma unroll
    for (int i = 0; i < 4; i++) {
        float r0[6], r1[6], r2[6];
#pragma unroll
        for (int j = 0; j < 6; j++) {
            r0[j] = tile[ty + i    ][tx + j];
            r1[j] = tile[ty + i + 1][tx + j];
            r2[j] = tile[ty + i + 2][tx + j];
        }
        float4 ov;
        float* op = (float*)&ov;
#pragma unroll
        for (int j = 0; j < 4; j++) {
            float s = 0.f;
            s = fmaf(wv[0], r0[j],     s);
            s = fmaf(wv[1], r0[j + 1], s);
            s = fmaf(wv[2], r0[j + 2], s);
            s = fmaf(wv[3], r1[j],     s);
            s = fmaf(wv[4], r1[j + 1], s);
            s = fmaf(wv[5], r1[j + 2], s);
            s = fmaf(wv[6], r2[j],     s);
            s = fmaf(wv[7], r2[j + 1], s);
            s = fmaf(wv[8], r2[j + 2], s);
            ssq = fmaf(s, s, ssq);
            op[j] = isqk ? s : cvt_tf32(s);
        }
        *(float4*)(o + (long)(y0 + ty + i) * WW + x0 + tx) = ov;
    }

    if (isqk) {
#pragma unroll
        for (int off = 16; off > 0; off >>= 1)
            ssq += __shfl_xor_sync(0xffffffffu, ssq, off);
        __shared__ float wsum[8];
        const int lane = tid & 31, wrp = tid >> 5;
        if (lane == 0) wsum[wrp] = ssq;
        __syncthreads();
        if (tid == 0) {
            float tot = 0.f;
#pragma unroll
            for (int i = 0; i < 8; i++) tot += wsum[i];
            atomicAdd(&g_sumsq[b * 2 * CDIM + c], tot);
        }
    }
}

// ---------------------------------------------------------------
// attn partials via tensor cores, split-tf32, direct GMEM fragment
// loads, chunk = 1024 cols -> grid 288 = one wave at 2 blocks/SM.
// grid: (ACH=36, BATCH*NH), block 256
// ---------------------------------------------------------------
__global__ __launch_bounds__(256, 2) void attn_kernel()
{
    const int bh = blockIdx.y;
    const int b = bh >> 2, h = bh & 3;
    const float* __restrict__ qbase = g_dw + ((long)b * OC3 + h * HD) * HWSZ;
    const float* __restrict__ kbase = g_dw + ((long)b * OC3 + CDIM + h * HD) * HWSZ;

    const int t = threadIdx.x;
    const int w = t >> 5, l = t & 31;
    const int g = l >> 2, q_ = l & 3;
    const int n0 = blockIdx.x * 1024 + w * 128;

    __shared__ float buf[HD * HD];
    for (int i = t; i < HD * HD; i += 256) buf[i] = 0.f;
    __syncthreads();

    float acc[3][6][4];
#pragma unroll
    for (int mt = 0; mt < 3; mt++)
#pragma unroll
        for (int nt = 0; nt < 6; nt++)
#pragma unroll
            for (int c = 0; c < 4; c++) acc[mt][nt][c] = 0.f;

    for (int ks = 0; ks < 16; ks++) {
        const int nn = n0 + ks * 8;
        unsigned ah[3][4], al[3][4], bhx[6][2], blx[6][2];
#pragma unroll
        for (int mt = 0; mt < 3; mt++) {
            const float* p0 = qbase + (long)(mt * 16 + g) * HWSZ + nn + q_;
            const float* p1 = p0 + 8 * HWSZ;
            float v0 = p0[0], v1 = p1[0], v2 = p0[4], v3 = p1[4];
            float h0 = cvt_tf32(v0), h1 = cvt_tf32(v1);
            float h2 = cvt_tf32(v2), h3 = cvt_tf32(v3);
            ah[mt][0] = __float_as_uint(h0); al[mt][0] = __float_as_uint(cvt_tf32(v0 - h0));
            ah[mt][1] = __float_as_uint(h1); al[mt][1] = __float_as_uint(cvt_tf32(v1 - h1));
            ah[mt][2] = __float_as_uint(h2); al[mt][2] = __float_as_uint(cvt_tf32(v2 - h2));
            ah[mt][3] = __float_as_uint(h3); al[mt][3] = __float_as_uint(cvt_tf32(v3 - h3));
        }
#pragma unroll
        for (int nt = 0; nt < 6; nt++) {
            const float* p = kbase + (long)(nt * 8 + g) * HWSZ + nn + q_;
            float v0 = p[0], v1 = p[4];
            float h0 = cvt_tf32(v0), h1 = cvt_tf32(v1);
            bhx[nt][0] = __float_as_uint(h0); blx[nt][0] = __float_as_uint(cvt_tf32(v0 - h0));
            bhx[nt][1] = __float_as_uint(h1); blx[nt][1] = __float_as_uint(cvt_tf32(v1 - h1));
        }
#pragma unroll
        for (int mt = 0; mt < 3; mt++)
#pragma unroll
            for (int nt = 0; nt < 6; nt++) {
                float* d = acc[mt][nt];
                asm volatile(
                    "mma.sync.aligned.m16n8k8.row.col.f32.tf32.tf32.f32 "
                    "{%0,%1,%2,%3}, {%4,%5,%6,%7}, {%8,%9}, {%0,%1,%2,%3};\n"
                    : "+f"(d[0]), "+f"(d[1]), "+f"(d[2]), "+f"(d[3])
                    : "r"(ah[mt][0]), "r"(ah[mt][1]), "r"(ah[mt][2]), "r"(ah[mt][3]),
                      "r"(bhx[nt][0]), "r"(bhx[nt][1]));
                asm volatile(
                    "mma.sync.aligned.m16n8k8.row.col.f32.tf32.tf32.f32 "
                    "{%0,%1,%2,%3}, {%4,%5,%6,%7}, {%8,%9}, {%0,%1,%2,%3};\n"
                    : "+f"(d[0]), "+f"(d[1]), "+f"(d[2]), "+f"(d[3])
                    : "r"(al[mt][0]), "r"(al[mt][1]), "r"(al[mt][2]), "r"(al[mt][3]),
                      "r"(bhx[nt][0]), "r"(bhx[nt][1]));
                asm volatile(
                    "mma.sync.aligned.m16n8k8.row.col.f32.tf32.tf32.f32 "
                    "{%0,%1,%2,%3}, {%4,%5,%6,%7}, {%8,%9}, {%0,%1,%2,%3};\n"
                    : "+f"(d[0]), "+f"(d[1]), "+f"(d[2]), "+f"(d[3])
                    : "r"(ah[mt][0]), "r"(ah[mt][1]), "r"(ah[mt][2]), "r"(ah[mt][3]),
                      "r"(blx[nt][0]), "r"(blx[nt][1]));
            }
    }

#pragma unroll
    for (int mt = 0; mt < 3; mt++)
#pragma unroll
        for (int nt = 0; nt < 6; nt++) {
            const int r0 = mt * 16 + g, c0 = nt * 8 + 2 * q_;
            atomicAdd(&buf[r0 * HD + c0],       acc[mt][nt][0]);
            atomicAdd(&buf[r0 * HD + c0 + 1],   acc[mt][nt][1]);
            atomicAdd(&buf[(r0+8) * HD + c0],   acc[mt][nt][2]);
            atomicAdd(&buf[(r0+8) * HD + c0+1], acc[mt][nt][3]);
        }
    __syncthreads();

    float* op = g_attn_part + ((long)bh * ACH + blockIdx.x) * HD * HD;
    for (int i = t; i < HD * HD; i += 256) op[i] = buf[i];
}

// ---------------------------------------------------------------
// parallel reduce of the ACH partials: grid (9, 8), 256 threads.
// ---------------------------------------------------------------
__global__ __launch_bounds__(256) void reduce_kernel()
{
    const int bh = blockIdx.y;
    const int cell = blockIdx.x * 256 + threadIdx.x;
    const float* pp = g_attn_part + (long)bh * ACH * HD * HD + cell;
    float s = 0.f;
#pragma unroll 6
    for (int c = 0; c < ACH; c++) s += pp[(long)c * HD * HD];
    g_attn_r[bh * HD * HD + cell] = s;
}

// ---------------------------------------------------------------
__global__ void softmax_kernel(const float* __restrict__ log_temp)
{
    const int bh = blockIdx.x;
    const int b = bh >> 2, h = bh & 3;
    __shared__ float nq[HD], nk[HD];
    const int t = threadIdx.x;
    if (t < HD) {
        nq[t] = fmaxf(sqrtf(g_sumsq[b * 2 * CDIM + h * HD + t]), 1e-12f);
        nk[t] = fmaxf(sqrtf(g_sumsq[b * 2 * CDIM + CDIM + h * HD + t]), 1e-12f);
    }
    __syncthreads();
    const float temp = log1pf(expf(log_temp[h])) + 1e-6f;
    if (t < HD) {
        float v[HD];
        const float* row = g_attn_r + (bh * HD + t) * HD;
        float mx = -1e30f;
        const float inq = temp / nq[t];
#pragma unroll 8
        for (int e = 0; e < HD; e++) {
            v[e] = row[e] * inq / nk[e];
            mx = fmaxf(mx, v[e]);
        }
        float ssum = 0.f;
#pragma unroll 8
        for (int e = 0; e < HD; e++) { v[e] = __expf(v[e] - mx); ssum += v[e]; }
        const float inv = 1.f / ssum;
        float* orow = g_attn_s + (bh * HD + t) * HD;
#pragma unroll 8
        for (int e = 0; e < HD; e++) orow[e] = v[e] * inv;
    }
}

// ---------------------------------------------------------------
__global__ void w2_kernel(const float* __restrict__ w_proj)
{
    const int bo = blockIdx.x;
    const int b = bo / CDIM, o = bo % CDIM;
    const int he = threadIdx.x;
    const int h = he / HD, e = he % HD;
    const float* wp = w_proj + o * CDIM + h * HD;
    const float* at = g_attn_s + ((long)(b * NH + h) * HD) * HD + e;
    float s = 0.f;
#pragma unroll 8
    for (int d = 0; d < HD; d++) s = fmaf(wp[d], at[d * HD], s);
    g_W2[((long)b * CDIM + o) * CDIM + he] = cvt_tf32(s);
}

// ---------------------------------------------------------------
extern "C" void kernel_launch(void* const* d_in, const int* in_sizes, int n_in,
                              void* d_out, int out_size)
{
    const float* x      = (const float*)d_in[0];
    const float* w_qkv  = (const float*)d_in[1];
    const float* w_dw   = (const float*)d_in[2];
    const float* w_proj = (const float*)d_in[3];
    const float* ltemp  = (const float*)d_in[4];
    float* out = (float*)d_out;

    float *p_qkv, *p_dw, *p_W2;
    cudaGetSymbolAddress((void**)&p_qkv, g_qkv);
    cudaGetSymbolAddress((void**)&p_dw,  g_dw);
    cudaGetSymbolAddress((void**)&p_W2,  g_W2);

    static int smem_set = 0;
    if (!smem_set) {
        cudaFuncSetAttribute(tf32_gemm_kernel<true>,
                             cudaFuncAttributeMaxDynamicSharedMemorySize,
                             GEMM_SMEM_BYTES);
        cudaFuncSetAttribute(tf32_gemm_kernel<false>,
                             cudaFuncAttributeMaxDynamicSharedMemorySize,
                             GEMM_SMEM_BYTES);
        smem_set = 1;
    }

    zero_kernel<<<3, 256>>>();

    // GEMM1: qkv = w_qkv @ x  (raw fp32 operands, cvt.rna at fragment load)
    tf32_gemm_kernel<true>
        <<<dim3(HWSZ / 256, OC3 / 64, BATCH), 256, GEMM_SMEM_BYTES>>>(
        w_qkv, x, p_qkv, 0L, (long)CDIM * HWSZ, (long)OC3 * HWSZ);

    // depthwise 3x3 + q/k sum-of-squares
    dw_kernel<<<dim3(3, 3, BATCH * OC3), 256>>>(w_dw);

    // attn partials (direct-GMEM tensor cores, split-tf32, 1 wave)
    attn_kernel<<<dim3(ACH, BATCH * NH), 256>>>();

    // parallel reduce, then normalize + temperature + softmax
    reduce_kernel<<<dim3(HD * HD / 256, BATCH * NH), 256>>>();
    softmax_kernel<<<BATCH * NH, 64>>>(ltemp);
    w2_kernel<<<BATCH * CDIM, 192>>>(w_proj);

    // GEMM2: out = W2[b] @ v[b]  (operands pre-rounded: W2 by w2, v by dw)
    tf32_gemm_kernel<false>
        <<<dim3(HWSZ / 256, CDIM / 64, BATCH), 256, GEMM_SMEM_BYTES>>>(
        p_W2, p_dw + (long)2 * CDIM * HWSZ, out,
        (long)CDIM * CDIM, (long)OC3 * HWSZ, (long)CDIM * HWSZ);
}